// round 16
// baseline (speedup 1.0000x reference)
#include <cuda_runtime.h>
#include <cuda_bf16.h>
#include <cstdint>

#define B_    4
#define C_    384
#define HW_   16384
#define NH_   8
#define HD_   48
#define NS2   32            // split-K for X2
#define XK_   (HW_ / NS2)   // 512

typedef unsigned long long u64;

// ---------------------------------------------------------------------------
// Scratch (device globals — no allocation allowed)
// ---------------------------------------------------------------------------
__device__ uint32_t g_x_hi[(size_t)B_ * C_ * HW_ / 2];
__device__ uint32_t g_x_lo[(size_t)B_ * C_ * HW_ / 2];
__device__ float    g_x2p[(size_t)NS2 * B_ * 6 * 128 * 128];
__device__ float    g_x2[(size_t)B_ * C_ * C_];
__device__ float    g_T[(size_t)B_ * 768 * C_];
__device__ float    g_weff[(size_t)B_ * C_ * C_];
__device__ uint32_t g_wf_hi[(size_t)B_ * C_ * C_ / 2];
__device__ uint32_t g_wf_lo[(size_t)B_ * C_ * C_ / 2];

// ---------------------------------------------------------------------------
// Helpers
// ---------------------------------------------------------------------------
__device__ __forceinline__ uint32_t smem_u32(const void* p) {
    uint32_t a;
    asm("{ .reg .u64 t; cvta.to.shared.u64 t, %1; cvt.u32.u64 %0, t; }" : "=r"(a) : "l"(p));
    return a;
}
__device__ __forceinline__ void split2(uint32_t& hi, uint32_t& lo, float f0, float f1) {
    uint32_t u0 = __float_as_uint(f0), u1 = __float_as_uint(f1);
    asm("prmt.b32 %0, %1, %2, 0x7632;" : "=r"(hi) : "r"(u0), "r"(u1));
    float h0 = __uint_as_float(u0 & 0xFFFF0000u);
    float h1 = __uint_as_float(u1 & 0xFFFF0000u);
    float l0 = f0 - h0, l1 = f1 - h1;
    asm("cvt.rn.bf16x2.f32 %0, %1, %2;" : "=r"(lo) : "f"(l1), "f"(l0));
}
__device__ __forceinline__ void ldsm4(uint32_t* r, uint32_t addr) {
    asm volatile("ldmatrix.sync.aligned.m8n8.x4.shared.b16 {%0,%1,%2,%3}, [%4];"
                 : "=r"(r[0]), "=r"(r[1]), "=r"(r[2]), "=r"(r[3]) : "r"(addr));
}
__device__ __forceinline__ void ldsm4t(uint32_t* r, uint32_t addr) {
    asm volatile("ldmatrix.sync.aligned.m8n8.x4.trans.shared.b16 {%0,%1,%2,%3}, [%4];"
                 : "=r"(r[0]), "=r"(r[1]), "=r"(r[2]), "=r"(r[3]) : "r"(addr));
}
__device__ __forceinline__ void mma16816(float* d, const uint32_t* a, const uint32_t* b) {
    asm volatile(
        "mma.sync.aligned.m16n8k16.row.col.f32.bf16.bf16.f32 "
        "{%0,%1,%2,%3}, {%4,%5,%6,%7}, {%8,%9}, {%0,%1,%2,%3};"
        : "+f"(d[0]), "+f"(d[1]), "+f"(d[2]), "+f"(d[3])
        : "r"(a[0]), "r"(a[1]), "r"(a[2]), "r"(a[3]), "r"(b[0]), "r"(b[1]));
}
__device__ __forceinline__ void cpa16(uint32_t dst, const void* src) {
    asm volatile("cp.async.cg.shared.global [%0], [%1], 16;" :: "r"(dst), "l"(src) : "memory");
}
#define CPA_COMMIT() asm volatile("cp.async.commit_group;" ::: "memory")
#define CPA_WAIT1()  asm volatile("cp.async.wait_group 1;"  ::: "memory")
#define CPA_WAIT0()  asm volatile("cp.async.wait_group 0;"  ::: "memory")

__device__ __forceinline__ u64 pk2(float lo, float hi) {
    u64 r; asm("mov.b64 %0, {%1,%2};" : "=l"(r) : "f"(lo), "f"(hi)); return r;
}
__device__ __forceinline__ void upk2(u64 v, float& lo, float& hi) {
    asm("mov.b64 {%0,%1}, %2;" : "=f"(lo), "=f"(hi) : "l"(v));
}
__device__ __forceinline__ u64 fma2(u64 a, u64 b, u64 c) {
    u64 d; asm("fma.rn.f32x2 %0, %1, %2, %3;" : "=l"(d) : "l"(a), "l"(b), "l"(c)); return d;
}

// ============================================================================
// K0: fp32 -> bf16 hi/lo planes
// ============================================================================
__global__ void __launch_bounds__(256)
split_planes(const float2* __restrict__ src, uint32_t* __restrict__ hp,
             uint32_t* __restrict__ lp, int n)
{
    for (int i = blockIdx.x * blockDim.x + threadIdx.x; i < n; i += gridDim.x * blockDim.x) {
        float2 v = src[i];
        uint32_t h, l;
        split2(h, l, v.x, v.y);
        hp[i] = h; lp[i] = l;
    }
}

// ============================================================================
// K1: X2 partials. 128x128 tile, BK=32, 2-stage cp.async, 2 CTAs/SM.
// Diagonal block-pairs (bi==bj) alias B tiles to the A region (skip B loads).
// Stage: A hi/lo + B hi/lo, each [128][40] halves (10240 B).
// ============================================================================
#define XP 10240
#define XSTG (4 * XP)
#define X2_SMEM (2 * XSTG)   // 81920 -> 2 CTAs/SM

__constant__ int c_BI[6] = {0, 0, 0, 1, 1, 2};
__constant__ int c_BJ[6] = {0, 1, 2, 1, 2, 2};

__global__ void __launch_bounds__(256, 2)
x2_cp(const __nv_bfloat16* __restrict__ Xh, const __nv_bfloat16* __restrict__ Xl)
{
    extern __shared__ char smem[];
    const uint32_t sb = smem_u32(smem);
    const int tid = threadIdx.x;
    const int wid = tid >> 5, lane = tid & 31;
    const int bp = blockIdx.x / NS2, split = blockIdx.x % NS2;
    const int b = blockIdx.y;
    const int bi = c_BI[bp], bj = c_BJ[bp];
    const bool diag = (bi == bj);
    const uint32_t boff = diag ? 0u : (uint32_t)(2 * XP);
    const size_t xbase = (size_t)b * C_ * HW_;
    const int k0base = split * XK_;
    const int warp_m = (wid >> 2) * 64, warp_n = (wid & 3) * 32;

    float acc[4][4][4];
#pragma unroll
    for (int i = 0; i < 4; i++)
#pragma unroll
        for (int j = 0; j < 4; j++)
#pragma unroll
            for (int p = 0; p < 4; p++) acc[i][j][p] = 0.0f;

    auto ISSUE = [&](int s, int c) {
        const int k0 = k0base + c * 32;
        const uint32_t stg = sb + s * XSTG;
#pragma unroll
        for (int i = 0; i < 8; i++) {
            int id = tid + 256 * i;              // 0..2047
            int pt = id >> 9;                    // 0:A_hi 1:A_lo 2:B_hi 3:B_lo
            if (diag && pt >= 2) continue;
            int rem = id & 511;
            int row = rem >> 2, ch = rem & 3;
            int chan = ((pt < 2) ? bi : bj) * 128 + row;
            const __nv_bfloat16* src =
                ((pt & 1) ? Xl : Xh) + xbase + (size_t)chan * HW_ + k0 + ch * 8;
            cpa16(stg + pt * XP + (uint32_t)((row * 40 + ch * 8) << 1), src);
        }
        CPA_COMMIT();
    };

    auto MMASTEP = [&](int s, int ks) {
        const uint32_t stg = sb + s * XSTG;
        const uint32_t koff = (uint32_t)(ks * 16 + ((lane >> 4) << 3));
        uint32_t bh[4][2], bl[4][2];
        {
            uint32_t bd = stg + boff + (((uint32_t)(warp_n + (lane & 15)) * 40 + koff) << 1);
            uint32_t r4[4];
            ldsm4(r4, bd);
            bh[0][0] = r4[0]; bh[0][1] = r4[2]; bh[1][0] = r4[1]; bh[1][1] = r4[3];
            ldsm4(r4, bd + (40 * 16 << 1));
            bh[2][0] = r4[0]; bh[2][1] = r4[2]; bh[3][0] = r4[1]; bh[3][1] = r4[3];
            uint32_t bdl = bd + XP;
            ldsm4(r4, bdl);
            bl[0][0] = r4[0]; bl[0][1] = r4[2]; bl[1][0] = r4[1]; bl[1][1] = r4[3];
            ldsm4(r4, bdl + (40 * 16 << 1));
            bl[2][0] = r4[0]; bl[2][1] = r4[2]; bl[3][0] = r4[1]; bl[3][1] = r4[3];
        }
#pragma unroll
        for (int mf = 0; mf < 4; mf++) {
            uint32_t ah[4], al[4];
            uint32_t ad = stg + (((uint32_t)(warp_m + mf * 16 + (lane & 15)) * 40 + koff) << 1);
            ldsm4(ah, ad);
            ldsm4(al, ad + XP);
#pragma unroll
            for (int nf = 0; nf < 4; nf++) {
                mma16816(acc[mf][nf], ah, bh[nf]);
                mma16816(acc[mf][nf], ah, bl[nf]);
                mma16816(acc[mf][nf], al, bh[nf]);
            }
        }
    };

    const int NC = XK_ >> 5;   // 16
    ISSUE(0, 0);
    for (int c = 0; c < NC; c++) {
        const int s = c & 1;
        if (c + 1 < NC) { ISSUE(1 - s, c + 1); CPA_WAIT1(); }
        else            { CPA_WAIT0(); }
        __syncthreads();
        MMASTEP(s, 0);
        MMASTEP(s, 1);
        __syncthreads();
    }

    float* pb = g_x2p + ((size_t)(b * NS2 + split) * 6 + bp) * 16384;
    const int g = lane >> 2, t2 = (lane & 3) * 2;
#pragma unroll
    for (int mf = 0; mf < 4; mf++)
#pragma unroll
        for (int nf = 0; nf < 4; nf++) {
            int r0 = warp_m + mf * 16 + g;
            int c0 = warp_n + nf * 8 + t2;
            pb[r0 * 128 + c0]           = acc[mf][nf][0];
            pb[r0 * 128 + c0 + 1]       = acc[mf][nf][1];
            pb[(r0 + 8) * 128 + c0]     = acc[mf][nf][2];
            pb[(r0 + 8) * 128 + c0 + 1] = acc[mf][nf][3];
        }
}

// ============================================================================
// K2: reduce split-K partials into full mirrored X2 [b][384][384].
// One block per (bp, b): coalesced float4 partial loads, mirrored store.
// ============================================================================
__global__ void __launch_bounds__(256)
x2_reduce()
{
    const int bp = blockIdx.x, b = blockIdx.y;
    const int bi = c_BI[bp], bj = c_BJ[bp];
    const int tid = threadIdx.x;
    float* x2b = g_x2 + (size_t)b * C_ * C_;

    for (int t = 0; t < 16; t++) {
        int base = t * 1024 + tid * 4;        // element index in 128x128 tile
        int li = base >> 7, lj = base & 127;
        float4 v = make_float4(0.f, 0.f, 0.f, 0.f);
#pragma unroll
        for (int sp = 0; sp < NS2; sp++) {
            float4 p = *reinterpret_cast<const float4*>(
                &g_x2p[((size_t)(b * NS2 + sp) * 6 + bp) * 16384 + base]);
            v.x += p.x; v.y += p.y; v.z += p.z; v.w += p.w;
        }
        int gi = bi * 128 + li, gj = bj * 128 + lj;
        *reinterpret_cast<float4*>(&x2b[(size_t)gi * C_ + gj]) = v;
        // mirror
        x2b[(size_t)(gj + 0) * C_ + gi] = v.x;
        x2b[(size_t)(gj + 1) * C_ + gi] = v.y;
        x2b[(size_t)(gj + 2) * C_ + gi] = v.z;
        x2b[(size_t)(gj + 3) * C_ + gi] = v.w;
    }
}

// ============================================================================
// K3: T_all[b] (768x384) = qkv_w[0:768] @ X2[b].  f32x2 GEMM, 3-stage cp.async.
// 32x64 tiles, grid (6, 24, 4) = 576 -> ~4 CTAs/SM.
// Stage: A [32][20] f32 (2560 B) + B [16][68] f32 (4352 B) = 6912 B.
// ============================================================================
#define TA_A_OFF 0
#define TA_B_OFF 2560
#define TA_STG   6912
#define TA_SMEM  (3 * TA_STG)   // 20736

__global__ void __launch_bounds__(256)
tA_gemm(const float* __restrict__ qkv_w)
{
    extern __shared__ char smem[];
    const uint32_t sb = smem_u32(smem);
    float* smf = reinterpret_cast<float*>(smem);
    const int b = blockIdx.z;
    const float* Bm = g_x2 + (size_t)b * C_ * C_;
    const int tm = blockIdx.y * 32, tn = blockIdx.x * 64;
    const int tid = threadIdx.x;
    const int tx = tid & 15, ty = tid >> 4;

    u64 acc[2][2];
    acc[0][0] = acc[0][1] = acc[1][0] = acc[1][1] = 0ull;

    auto ISSUE = [&](int s, int c) {
        const int k0 = c * 16;
        const uint32_t stg = sb + s * TA_STG;
        if (tid < 128) {   // A tile 32x16 f32 = 128 x 16B chunks
            int r = tid >> 2, c4 = (tid & 3) << 2;
            cpa16(stg + TA_A_OFF + (uint32_t)((r * 20 + c4) << 2),
                  &qkv_w[(size_t)(tm + r) * C_ + k0 + c4]);
        }
        {   // B tile 16x64 f32 = 256 x 16B chunks
            int r = tid >> 4, c4 = (tid & 15) << 2;
            cpa16(stg + TA_B_OFF + (uint32_t)((r * 68 + c4) << 2),
                  &Bm[(size_t)(k0 + r) * C_ + tn + c4]);
        }
        CPA_COMMIT();
    };

    auto MMACHUNK = [&](int s) {
        const float* As = smf + (s * TA_STG + TA_A_OFF) / 4;
        const float* Bs = smf + (s * TA_STG + TA_B_OFF) / 4;
#pragma unroll
        for (int kk = 0; kk < 16; kk++) {
            u64 bv0, bv1;
            const u64* bp = reinterpret_cast<const u64*>(&Bs[kk * 68 + tx * 4]);
            bv0 = bp[0]; bv1 = bp[1];
#pragma unroll
            for (int i = 0; i < 2; i++) {
                float a = As[(ty * 2 + i) * 20 + kk];
                u64 av = pk2(a, a);
                acc[i][0] = fma2(av, bv0, acc[i][0]);
                acc[i][1] = fma2(av, bv1, acc[i][1]);
            }
        }
    };

    const int NC = C_ / 16;   // 24
    ISSUE(0, 0);
    ISSUE(1, 1);
    for (int c = 0; c < NC; c++) {
        const int s = c % 3;
        if (c == NC - 1) { CPA_WAIT0(); } else { CPA_WAIT1(); }
        __syncthreads();
        if (c + 2 < NC) ISSUE((c + 2) % 3, c + 2);
        MMACHUNK(s);
    }

    float* T = g_T + (size_t)b * 768 * C_;
#pragma unroll
    for (int i = 0; i < 2; i++) {
        int row = tm + ty * 2 + i;
        float o[4];
        upk2(acc[i][0], o[0], o[1]);
        upk2(acc[i][1], o[2], o[3]);
        *reinterpret_cast<float4*>(&T[(size_t)row * C_ + tn + tx * 4]) =
            make_float4(o[0], o[1], o[2], o[3]);
    }
}

// ============================================================================
// K4: per (b,h): Gqk + norms from T_all, softmax, fold attn into proj_w slice.
// ============================================================================
#define TB_OWK  0
#define TB_OG   18480
#define TB_OINV 20784
#define TB_OATT 20880
#define TB_OPW  23184
#define TB_SMEM ((TB_OPW + 384 * 49) * 4)

__global__ void __launch_bounds__(256)
tB_kernel(const float* __restrict__ temperature,
          const float* __restrict__ proj_w,
          const float* __restrict__ qkv_w)
{
    extern __shared__ float sm[];
    float* sWk   = sm + TB_OWK;
    float* sG    = sm + TB_OG;
    float* sInv  = sm + TB_OINV;
    float* sAttn = sm + TB_OATT;
    float* spw   = sm + TB_OPW;

    const int bh = blockIdx.x;
    const int b = bh >> 3, h = bh & 7;
    const int tid = threadIdx.x;
    const float* Tq = g_T + (size_t)b * 768 * C_ + (size_t)h * HD_ * C_;
    const float* Tk = g_T + (size_t)b * 768 * C_ + (size_t)(C_ + h * HD_) * C_;

    for (int idx = tid; idx < 48 * C_; idx += 256) {
        int e = idx / C_, k = idx % C_;
        sWk[e * 385 + k] = qkv_w[(size_t)(C_ + h * HD_ + e) * C_ + k];
    }
    for (int idx = tid; idx < 384 * 12; idx += 256) {
        int o = idx / 12, d4 = (idx % 12) * 4;
        float4 v = *reinterpret_cast<const float4*>(&proj_w[(size_t)o * C_ + h * 48 + d4]);
        float* dst = &spw[o * 49 + d4];
        dst[0] = v.x; dst[1] = v.y; dst[2] = v.z; dst[3] = v.w;
    }
    __syncthreads();

    for (int idx = tid; idx < 48 * 48; idx += 256) {
        int d = idx / 48, e = idx % 48;
        const float* tr = &Tq[(size_t)d * C_];
        const float* wr = &sWk[e * 385];
        float s = 0.0f;
#pragma unroll 8
        for (int k = 0; k < C_; k++) s += tr[k] * wr[k];
        sG[idx] = s;
    }
    if (tid < 96) {
        float s = 0.0f;
        if (tid < 48) {
            const float* tr = &Tq[(size_t)tid * C_];
            const float* wq = &qkv_w[(size_t)(h * HD_ + tid) * C_];
#pragma unroll 8
            for (int k = 0; k < C_; k++) s += tr[k] * wq[k];
        } else {
            int e = tid - 48;
            const float* tr = &Tk[(size_t)e * C_];
            const float* wr = &sWk[e * 385];
#pragma unroll 8
            for (int k = 0; k < C_; k++) s += tr[k] * wr[k];
        }
        sInv[tid] = 1.0f / fmaxf(sqrtf(s), 1e-12f);
    }
    __syncthreads();

    const float temp = temperature[h];
    if (tid < 48) {
        int d = tid;
        float l[48];
        float mx = -1e30f;
#pragma unroll
        for (int e = 0; e < 48; e++) {
            float v = sG[d * 48 + e] * sInv[d] * sInv[48 + e] * temp;
            l[e] = v;
            mx = fmaxf(mx, v);
        }
        float sum = 0.0f;
#pragma unroll
        for (int e = 0; e < 48; e++) { l[e] = expf(l[e] - mx); sum += l[e]; }
        float inv = 1.0f / sum;
#pragma unroll
        for (int e = 0; e < 48; e++) sAttn[d * 48 + e] = l[e] * inv;
    }
    __syncthreads();

    for (int o = tid; o < 384; o += 256) {
        const float* pw = &spw[o * 49];
        float* wout = &g_weff[((size_t)b * C_ + o) * C_ + h * 48];
#pragma unroll
        for (int eb = 0; eb < 6; eb++) {
            float a0 = 0, a1 = 0, a2 = 0, a3 = 0, a4 = 0, a5 = 0, a6 = 0, a7 = 0;
#pragma unroll 8
            for (int d = 0; d < 48; d++) {
                float p = pw[d];
                const float* ar = &sAttn[d * 48 + eb * 8];
                a0 += p * ar[0]; a1 += p * ar[1]; a2 += p * ar[2]; a3 += p * ar[3];
                a4 += p * ar[4]; a5 += p * ar[5]; a6 += p * ar[6]; a7 += p * ar[7];
            }
            wout[eb * 8 + 0] = a0; wout[eb * 8 + 1] = a1;
            wout[eb * 8 + 2] = a2; wout[eb * 8 + 3] = a3;
            wout[eb * 8 + 4] = a4; wout[eb * 8 + 5] = a5;
            wout[eb * 8 + 6] = a6; wout[eb * 8 + 7] = a7;
        }
    }
}

// ============================================================================
// K5: W_final[b] = W_eff[b] @ W_v -> bf16 planes. f32x2 GEMM 128x128.
// ============================================================================
__global__ void __launch_bounds__(256)
wfinal_kernel(const float* __restrict__ qkv_w)
{
    const int BM = 128, BN = 128, BK = 16;
    __shared__ __align__(16) float As[BK][BM];
    __shared__ __align__(16) float Bs[BK][BN];

    const int b = blockIdx.z;
    const float* A = g_weff + (size_t)b * C_ * C_;
    const float* Bm = qkv_w + (size_t)2 * C_ * C_;
    const int tm = blockIdx.y * BM, tn = blockIdx.x * BN;
    const int tid = threadIdx.x;
    const int tx = tid & 15, ty = tid >> 4;

    u64 acc[8][4];
#pragma unroll
    for (int i = 0; i < 8; i++)
#pragma unroll
        for (int p = 0; p < 4; p++) acc[i][p] = 0ull;

    for (int k0 = 0; k0 < C_; k0 += BK) {
#pragma unroll
        for (int i = 0; i < 2; i++) {
            int f4 = tid + 256 * i;
            int r = f4 >> 2, c4 = (f4 & 3) << 2;
            float4 v = *reinterpret_cast<const float4*>(&A[(size_t)(tm + r) * C_ + k0 + c4]);
            As[c4 + 0][r] = v.x; As[c4 + 1][r] = v.y;
            As[c4 + 2][r] = v.z; As[c4 + 3][r] = v.w;
        }
#pragma unroll
        for (int i = 0; i < 2; i++) {
            int f4 = tid + 256 * i;
            int r = f4 >> 5, c4 = (f4 & 31) << 2;
            *reinterpret_cast<float4*>(&Bs[r][c4]) =
                *reinterpret_cast<const float4*>(&Bm[(size_t)(k0 + r) * C_ + tn + c4]);
        }
        __syncthreads();
#pragma unroll
        for (int kk = 0; kk < BK; kk++) {
            u64 av[8];
#pragma unroll
            for (int i = 0; i < 8; i++) { float a = As[kk][ty * 8 + i]; av[i] = pk2(a, a); }
            u64 bv[4];
            const u64* bp = reinterpret_cast<const u64*>(&Bs[kk][tx * 8]);
#pragma unroll
            for (int p = 0; p < 4; p++) bv[p] = bp[p];
#pragma unroll
            for (int i = 0; i < 8; i++)
#pragma unroll
                for (int p = 0; p < 4; p++)
                    acc[i][p] = fma2(av[i], bv[p], acc[i][p]);
        }
        __syncthreads();
    }

#pragma unroll
    for (int i = 0; i < 8; i++) {
        int row = tm + ty * 8 + i;
        float o[8];
#pragma unroll
        for (int p = 0; p < 4; p++) upk2(acc[i][p], o[2 * p], o[2 * p + 1]);
        uint32_t h0, l0, h1, l1, h2, l2, h3, l3;
        split2(h0, l0, o[0], o[1]);
        split2(h1, l1, o[2], o[3]);
        split2(h2, l2, o[4], o[5]);
        split2(h3, l3, o[6], o[7]);
        size_t ro = ((size_t)b * C_ + row) * (C_ / 2) + ((tn + tx * 8) >> 1);
        *reinterpret_cast<uint4*>(g_wf_hi + ro) = make_uint4(h0, h1, h2, h3);
        *reinterpret_cast<uint4*>(g_wf_lo + ro) = make_uint4(l0, l1, l2, l3);
    }
}

// ===========================================================================
// K6: out[b] = W_final[b] @ x[b] + proj_b.  128x128 tile, BK=32, 3-stage
// cp.async, 2 CTAs/SM. Stage: A hi/lo [128][40]h + B hi/lo [32][136]h.
// ===========================================================================
#define OA_HI 0
#define OA_LO 10240
#define OB_HI 20480
#define OB_LO 29184
#define OSTG  37888
#define GEMM_SMEM (3 * OSTG)   // 113664 -> 2 CTAs/SM

__global__ void __launch_bounds__(256, 2)
gemm_out(const __nv_bfloat16* __restrict__ Ah, const __nv_bfloat16* __restrict__ Al,
         const __nv_bfloat16* __restrict__ Bh, const __nv_bfloat16* __restrict__ Bl,
         int M, int N, int K, long long sA, long long sB,
         float* __restrict__ Of, long long sC, const float* __restrict__ bias)
{
    extern __shared__ char smem[];
    const uint32_t sb = smem_u32(smem);
    const int tid = threadIdx.x;
    const int wid = tid >> 5, lane = tid & 31;

    const int z = blockIdx.z;
    Ah += (size_t)z * sA;  Al += (size_t)z * sA;
    Bh += (size_t)z * sB;  Bl += (size_t)z * sB;
    const int tm = blockIdx.x * 128, tn = blockIdx.y * 128;
    const int warp_m = (wid >> 2) * 64, warp_n = (wid & 3) * 32;

    float acc[4][4][4];
#pragma unroll
    for (int i = 0; i < 4; i++)
#pragma unroll
        for (int j = 0; j < 4; j++)
#pragma unroll
            for (int p = 0; p < 4; p++) acc[i][j][p] = 0.0f;

    auto ISSUE = [&](int s, int c) {
        const int k0 = c * 32;
        const uint32_t stg = sb + s * OSTG;
#pragma unroll
        for (int i = 0; i < 4; i++) {
            int id = tid + 256 * i;
            int pl = id >> 9, rem = id & 511, row = rem >> 2, ch = rem & 3;
            const __nv_bfloat16* src = (pl ? Al : Ah) + (size_t)(tm + row) * K + k0 + ch * 8;
            cpa16(stg + OA_HI + pl * (OA_LO - OA_HI) + (uint32_t)((row * 40 + ch * 8) << 1), src);
        }
#pragma unroll
        for (int i = 0; i < 4; i++) {
            int id = tid + 256 * i;
            int pl = id >> 9, rem = id & 511, row = rem >> 4, ch = rem & 15;
            const __nv_bfloat16* src = (pl ? Bl : Bh) + (size_t)(k0 + row) * N + tn + ch * 8;
            cpa16(stg + OB_HI + pl * (OB_LO - OB_HI) + (uint32_t)((row * 136 + ch * 8) << 1), src);
        }
        CPA_COMMIT();
    };

    auto MMASTEP = [&](int s, int ks) {
        const uint32_t stg = sb + s * OSTG;
        uint32_t bh[4][2], bl[4][2];
        {
            uint32_t krow = (uint32_t)(ks * 16 + (lane & 7) + (((lane >> 3) & 1) << 3));
            uint32_t ncol = (uint32_t)(warp_n + ((lane >> 4) << 3));
            uint32_t bd  = stg + OB_HI + ((krow * 136 + ncol) << 1);
            uint32_t bdl = bd + (OB_LO - OB_HI);
            uint32_t r4[4];
            ldsm4t(r4, bd);
            bh[0][0] = r4[0]; bh[0][1] = r4[1]; bh[1][0] = r4[2]; bh[1][1] = r4[3];
            ldsm4t(r4, bd + 32);
            bh[2][0] = r4[0]; bh[2][1] = r4[1]; bh[3][0] = r4[2]; bh[3][1] = r4[3];
            ldsm4t(r4, bdl);
            bl[0][0] = r4[0]; bl[0][1] = r4[1]; bl[1][0] = r4[2]; bl[1][1] = r4[3];
            ldsm4t(r4, bdl + 32);
            bl[2][0] = r4[0]; bl[2][1] = r4[1]; bl[3][0] = r4[2]; bl[3][1] = r4[3];
        }
        const uint32_t arow = (uint32_t)(warp_m + (lane & 15));
        const uint32_t akoff = (uint32_t)(ks * 16 + ((lane >> 4) << 3));
#pragma unroll
        for (int mf = 0; mf < 4; mf++) {
            uint32_t ah[4], al[4];
            uint32_t ad = stg + OA_HI + (((arow + mf * 16) * 40 + akoff) << 1);
            ldsm4(ah, ad);
            ldsm4(al, ad + (OA_LO - OA_HI));
#pragma unroll
            for (int nf = 0; nf < 4; nf++) {
                mma16816(acc[mf][nf], ah, bh[nf]);
                mma16816(acc[mf][nf], ah, bl[nf]);
                mma16816(acc[mf][nf], al, bh[nf]);
            }
        }
    };

    const int NC = K >> 5;   // 12
    ISSUE(0, 0);
    ISSUE(1, 1);
    for (int c = 0; c < NC; c++) {
        const int s = c % 3;
        if (c == NC - 1) { CPA_WAIT0(); } else { CPA_WAIT1(); }
        __syncthreads();
        if (c + 2 < NC) ISSUE((c + 2) % 3, c + 2);
        MMASTEP(s, 0);
        MMASTEP(s, 1);
        __syncthreads();
    }

    // Epilogue staged via smem fp32 [128][132]
    float* cs = reinterpret_cast<float*>(smem);
    const int g = lane >> 2, t2 = (lane & 3) * 2;
#pragma unroll
    for (int mf = 0; mf < 4; mf++)
#pragma unroll
        for (int nf = 0; nf < 4; nf++) {
            int r0 = warp_m + mf * 16 + g;
            int c0 = warp_n + nf * 8 + t2;
            cs[r0 * 132 + c0]           = acc[mf][nf][0];
            cs[r0 * 132 + c0 + 1]       = acc[mf][nf][1];
            cs[(r0 + 8) * 132 + c0]     = acc[mf][nf][2];
            cs[(r0 + 8) * 132 + c0 + 1] = acc[mf][nf][3];
        }
    __syncthreads();
    {
        const int r = tid >> 1, cb = (tid & 1) * 64;
        const float bval = bias[tm + r];
        float* op = Of + (size_t)z * sC + (size_t)(tm + r) * N + tn + cb;
        const float* ip = &cs[r * 132 + cb];
#pragma unroll
        for (int j = 0; j < 16; j++) {
            float4 v = make_float4(ip[4 * j] + bval, ip[4 * j + 1] + bval,
                                   ip[4 * j + 2] + bval, ip[4 * j + 3] + bval);
            reinterpret_cast<float4*>(op)[j] = v;
        }
    }
}

// ============================================================================
extern "C" void kernel_launch(void* const* d_in, const int* in_sizes, int n_in,
                              void* d_out, int out_size)
{
    const float* x           = (const float*)d_in[0];
    const float* qkv_w       = (const float*)d_in[1];
    const float* proj_w      = (const float*)d_in[2];
    const float* proj_b      = (const float*)d_in[3];
    const float* temperature = (const float*)d_in[4];
    float* out = (float*)d_out;

    void* p;
    cudaGetSymbolAddress(&p, g_x_hi);  uint32_t* x_hi = (uint32_t*)p;
    cudaGetSymbolAddress(&p, g_x_lo);  uint32_t* x_lo = (uint32_t*)p;
    cudaGetSymbolAddress(&p, g_wf_hi); uint32_t* wf_hi = (uint32_t*)p;
    cudaGetSymbolAddress(&p, g_wf_lo); uint32_t* wf_lo = (uint32_t*)p;

    cudaFuncSetAttribute((const void*)x2_cp,
                         cudaFuncAttributeMaxDynamicSharedMemorySize, X2_SMEM);
    cudaFuncSetAttribute((const void*)tA_gemm,
                         cudaFuncAttributeMaxDynamicSharedMemorySize, TA_SMEM);
    cudaFuncSetAttribute((const void*)tB_kernel,
                         cudaFuncAttributeMaxDynamicSharedMemorySize, TB_SMEM);
    cudaFuncSetAttribute((const void*)gemm_out,
                         cudaFuncAttributeMaxDynamicSharedMemorySize, GEMM_SMEM);

    // K0: x -> bf16 hi/lo planes
    split_planes<<<2048, 256>>>((const float2*)x, x_hi, x_lo, B_ * C_ * HW_ / 2);

    // K1: X2 upper-block partials (Gram of x)
    x2_cp<<<dim3(6 * NS2, B_), 256, X2_SMEM>>>(
        (const __nv_bfloat16*)x_hi, (const __nv_bfloat16*)x_lo);

    // K2: reduce + mirror
    x2_reduce<<<dim3(6, B_), 256>>>();

    // K3: T_all = qkv_w[0:768] @ X2
    tA_gemm<<<dim3(6, 24, B_), 256, TA_SMEM>>>(qkv_w);

    // K4: Gram->softmax->W_eff fold
    tB_kernel<<<B_ * NH_, 256, TB_SMEM>>>(temperature, proj_w, qkv_w);

    // K5: W_final = W_eff @ W_v  -> bf16 planes
    wfinal_kernel<<<dim3(3, 3, B_), 256>>>(qkv_w);

    // K6: out = W_final @ x + proj_b
    gemm_out<<<dim3(C_ / 128, HW_ / 128, B_), 256, GEMM_SMEM>>>(
        (const __nv_bfloat16*)wf_hi, (const __nv_bfloat16*)wf_lo,
        (const __nv_bfloat16*)x_hi, (const __nv_bfloat16*)x_lo,
        C_, HW_, C_, (long long)C_ * C_, (long long)C_ * HW_,
        out, (long long)C_ * HW_, proj_b);
}

// round 17
// speedup vs baseline: 1.1186x; 1.1186x over previous
#include <cuda_runtime.h>
#include <cuda_bf16.h>
#include <cstdint>

#define B_    4
#define C_    384
#define HW_   16384
#define NH_   8
#define HD_   48
#define NS2   32            // split-K for X2
#define XK_   (HW_ / NS2)   // 512

typedef unsigned long long u64;

// ---------------------------------------------------------------------------
// Scratch (device globals — no allocation allowed)
// ---------------------------------------------------------------------------
__device__ uint32_t g_x_hi[(size_t)B_ * C_ * HW_ / 2];
__device__ uint32_t g_x_lo[(size_t)B_ * C_ * HW_ / 2];
__device__ float    g_x2p[(size_t)NS2 * B_ * 6 * 128 * 128];
__device__ float    g_x2[(size_t)B_ * C_ * C_];
__device__ float    g_T[(size_t)B_ * 768 * C_];
__device__ float    g_weff[(size_t)B_ * C_ * C_];
__device__ uint32_t g_wf_hi[(size_t)B_ * C_ * C_ / 2];
__device__ uint32_t g_wf_lo[(size_t)B_ * C_ * C_ / 2];

// ---------------------------------------------------------------------------
// Helpers
// ---------------------------------------------------------------------------
__device__ __forceinline__ uint32_t smem_u32(const void* p) {
    uint32_t a;
    asm("{ .reg .u64 t; cvta.to.shared.u64 t, %1; cvt.u32.u64 %0, t; }" : "=r"(a) : "l"(p));
    return a;
}
__device__ __forceinline__ void split2(uint32_t& hi, uint32_t& lo, float f0, float f1) {
    uint32_t u0 = __float_as_uint(f0), u1 = __float_as_uint(f1);
    asm("prmt.b32 %0, %1, %2, 0x7632;" : "=r"(hi) : "r"(u0), "r"(u1));
    float h0 = __uint_as_float(u0 & 0xFFFF0000u);
    float h1 = __uint_as_float(u1 & 0xFFFF0000u);
    float l0 = f0 - h0, l1 = f1 - h1;
    asm("cvt.rn.bf16x2.f32 %0, %1, %2;" : "=r"(lo) : "f"(l1), "f"(l0));
}
__device__ __forceinline__ void ldsm4(uint32_t* r, uint32_t addr) {
    asm volatile("ldmatrix.sync.aligned.m8n8.x4.shared.b16 {%0,%1,%2,%3}, [%4];"
                 : "=r"(r[0]), "=r"(r[1]), "=r"(r[2]), "=r"(r[3]) : "r"(addr));
}
__device__ __forceinline__ void ldsm4t(uint32_t* r, uint32_t addr) {
    asm volatile("ldmatrix.sync.aligned.m8n8.x4.trans.shared.b16 {%0,%1,%2,%3}, [%4];"
                 : "=r"(r[0]), "=r"(r[1]), "=r"(r[2]), "=r"(r[3]) : "r"(addr));
}
__device__ __forceinline__ void mma16816(float* d, const uint32_t* a, const uint32_t* b) {
    asm volatile(
        "mma.sync.aligned.m16n8k16.row.col.f32.bf16.bf16.f32 "
        "{%0,%1,%2,%3}, {%4,%5,%6,%7}, {%8,%9}, {%0,%1,%2,%3};"
        : "+f"(d[0]), "+f"(d[1]), "+f"(d[2]), "+f"(d[3])
        : "r"(a[0]), "r"(a[1]), "r"(a[2]), "r"(a[3]), "r"(b[0]), "r"(b[1]));
}
__device__ __forceinline__ void cpa16(uint32_t dst, const void* src) {
    asm volatile("cp.async.cg.shared.global [%0], [%1], 16;" :: "r"(dst), "l"(src) : "memory");
}
#define CPA_COMMIT() asm volatile("cp.async.commit_group;" ::: "memory")
#define CPA_WAIT1()  asm volatile("cp.async.wait_group 1;"  ::: "memory")
#define CPA_WAIT0()  asm volatile("cp.async.wait_group 0;"  ::: "memory")

__device__ __forceinline__ u64 pk2(float lo, float hi) {
    u64 r; asm("mov.b64 %0, {%1,%2};" : "=l"(r) : "f"(lo), "f"(hi)); return r;
}
__device__ __forceinline__ void upk2(u64 v, float& lo, float& hi) {
    asm("mov.b64 {%0,%1}, %2;" : "=f"(lo), "=f"(hi) : "l"(v));
}
__device__ __forceinline__ u64 fma2(u64 a, u64 b, u64 c) {
    u64 d; asm("fma.rn.f32x2 %0, %1, %2, %3;" : "=l"(d) : "l"(a), "l"(b), "l"(c)); return d;
}

// ============================================================================
// K0: fp32 -> bf16 hi/lo planes
// ============================================================================
__global__ void __launch_bounds__(256)
split_planes(const float2* __restrict__ src, uint32_t* __restrict__ hp,
             uint32_t* __restrict__ lp, int n)
{
    for (int i = blockIdx.x * blockDim.x + threadIdx.x; i < n; i += gridDim.x * blockDim.x) {
        float2 v = src[i];
        uint32_t h, l;
        split2(h, l, v.x, v.y);
        hp[i] = h; lp[i] = l;
    }
}

// ============================================================================
// K1: X2 partials. 128x128 tile, BK=32, 2-stage cp.async, 2 CTAs/SM.
// Diagonal block-pairs (bi==bj) alias B tiles to the A region (skip B loads).
// Stage: A hi/lo + B hi/lo, each [128][40] halves (10240 B).
// ============================================================================
#define XP 10240
#define XSTG (4 * XP)
#define X2_SMEM (2 * XSTG)   // 81920 -> 2 CTAs/SM

__constant__ int c_BI[6] = {0, 0, 0, 1, 1, 2};
__constant__ int c_BJ[6] = {0, 1, 2, 1, 2, 2};

__global__ void __launch_bounds__(256, 2)
x2_cp(const __nv_bfloat16* __restrict__ Xh, const __nv_bfloat16* __restrict__ Xl)
{
    extern __shared__ char smem[];
    const uint32_t sb = smem_u32(smem);
    const int tid = threadIdx.x;
    const int wid = tid >> 5, lane = tid & 31;
    const int bp = blockIdx.x / NS2, split = blockIdx.x % NS2;
    const int b = blockIdx.y;
    const int bi = c_BI[bp], bj = c_BJ[bp];
    const bool diag = (bi == bj);
    const uint32_t boff = diag ? 0u : (uint32_t)(2 * XP);
    const size_t xbase = (size_t)b * C_ * HW_;
    const int k0base = split * XK_;
    const int warp_m = (wid >> 2) * 64, warp_n = (wid & 3) * 32;

    float acc[4][4][4];
#pragma unroll
    for (int i = 0; i < 4; i++)
#pragma unroll
        for (int j = 0; j < 4; j++)
#pragma unroll
            for (int p = 0; p < 4; p++) acc[i][j][p] = 0.0f;

    auto ISSUE = [&](int s, int c) {
        const int k0 = k0base + c * 32;
        const uint32_t stg = sb + s * XSTG;
#pragma unroll
        for (int i = 0; i < 8; i++) {
            int id = tid + 256 * i;              // 0..2047
            int pt = id >> 9;                    // 0:A_hi 1:A_lo 2:B_hi 3:B_lo
            if (diag && pt >= 2) continue;
            int rem = id & 511;
            int row = rem >> 2, ch = rem & 3;
            int chan = ((pt < 2) ? bi : bj) * 128 + row;
            const __nv_bfloat16* src =
                ((pt & 1) ? Xl : Xh) + xbase + (size_t)chan * HW_ + k0 + ch * 8;
            cpa16(stg + pt * XP + (uint32_t)((row * 40 + ch * 8) << 1), src);
        }
        CPA_COMMIT();
    };

    auto MMASTEP = [&](int s, int ks) {
        const uint32_t stg = sb + s * XSTG;
        const uint32_t koff = (uint32_t)(ks * 16 + ((lane >> 4) << 3));
        uint32_t bh[4][2], bl[4][2];
        {
            uint32_t bd = stg + boff + (((uint32_t)(warp_n + (lane & 15)) * 40 + koff) << 1);
            uint32_t r4[4];
            ldsm4(r4, bd);
            bh[0][0] = r4[0]; bh[0][1] = r4[2]; bh[1][0] = r4[1]; bh[1][1] = r4[3];
            ldsm4(r4, bd + (40 * 16 << 1));
            bh[2][0] = r4[0]; bh[2][1] = r4[2]; bh[3][0] = r4[1]; bh[3][1] = r4[3];
            uint32_t bdl = bd + XP;
            ldsm4(r4, bdl);
            bl[0][0] = r4[0]; bl[0][1] = r4[2]; bl[1][0] = r4[1]; bl[1][1] = r4[3];
            ldsm4(r4, bdl + (40 * 16 << 1));
            bl[2][0] = r4[0]; bl[2][1] = r4[2]; bl[3][0] = r4[1]; bl[3][1] = r4[3];
        }
#pragma unroll
        for (int mf = 0; mf < 4; mf++) {
            uint32_t ah[4], al[4];
            uint32_t ad = stg + (((uint32_t)(warp_m + mf * 16 + (lane & 15)) * 40 + koff) << 1);
            ldsm4(ah, ad);
            ldsm4(al, ad + XP);
#pragma unroll
            for (int nf = 0; nf < 4; nf++) {
                mma16816(acc[mf][nf], ah, bh[nf]);
                mma16816(acc[mf][nf], ah, bl[nf]);
                mma16816(acc[mf][nf], al, bh[nf]);
            }
        }
    };

    const int NC = XK_ >> 5;   // 16
    ISSUE(0, 0);
    for (int c = 0; c < NC; c++) {
        const int s = c & 1;
        if (c + 1 < NC) { ISSUE(1 - s, c + 1); CPA_WAIT1(); }
        else            { CPA_WAIT0(); }
        __syncthreads();
        MMASTEP(s, 0);
        MMASTEP(s, 1);
        __syncthreads();
    }

    float* pb = g_x2p + ((size_t)(b * NS2 + split) * 6 + bp) * 16384;
    const int g = lane >> 2, t2 = (lane & 3) * 2;
#pragma unroll
    for (int mf = 0; mf < 4; mf++)
#pragma unroll
        for (int nf = 0; nf < 4; nf++) {
            int r0 = warp_m + mf * 16 + g;
            int c0 = warp_n + nf * 8 + t2;
            pb[r0 * 128 + c0]           = acc[mf][nf][0];
            pb[r0 * 128 + c0 + 1]       = acc[mf][nf][1];
            pb[(r0 + 8) * 128 + c0]     = acc[mf][nf][2];
            pb[(r0 + 8) * 128 + c0 + 1] = acc[mf][nf][3];
        }
}

// ============================================================================
// K2: reduce split-K partials into full mirrored X2 [b][384][384]
// (R15 per-element version: grid 2304, coalesced)
// ============================================================================
__global__ void __launch_bounds__(256)
x2_reduce()
{
    int idx = blockIdx.x * 256 + threadIdx.x;
    int b = idx / (C_ * C_);
    int rem = idx % (C_ * C_);
    int i = rem / C_, j = rem % C_;
    int bi = i >> 7, bj = j >> 7;
    int li, lj;
    int bp;
    if (bi <= bj) { bp = bi * 3 - bi * (bi - 1) / 2 + (bj - bi); li = i & 127; lj = j & 127; }
    else          { bp = bj * 3 - bj * (bj - 1) / 2 + (bi - bj); li = j & 127; lj = i & 127; }
    float s = 0.0f;
#pragma unroll
    for (int sp = 0; sp < NS2; sp++)
        s += g_x2p[((size_t)(b * NS2 + sp) * 6 + bp) * 16384 + li * 128 + lj];
    g_x2[idx] = s;
}

// ============================================================================
// K3: T_all[b] (768x384) = qkv_w[0:768] @ X2[b].  f32x2 GEMM, 3-stage cp.async.
// (R15 version: 64x64 tiles, grid (6,12,4)=288)
// ============================================================================
#define TA_A_OFF 0
#define TA_B_OFF 5120
#define TA_STG   9472
#define TA_SMEM  (3 * TA_STG)

__global__ void __launch_bounds__(256)
tA_gemm(const float* __restrict__ qkv_w)
{
    extern __shared__ char smem[];
    const uint32_t sb = smem_u32(smem);
    float* smf = reinterpret_cast<float*>(smem);
    const int b = blockIdx.z;
    const float* Bm = g_x2 + (size_t)b * C_ * C_;
    const int tm = blockIdx.y * 64, tn = blockIdx.x * 64;
    const int tid = threadIdx.x;
    const int tx = tid & 15, ty = tid >> 4;

    u64 acc[4][2];
#pragma unroll
    for (int i = 0; i < 4; i++) { acc[i][0] = 0ull; acc[i][1] = 0ull; }

    auto ISSUE = [&](int s, int c) {
        const int k0 = c * 16;
        const uint32_t stg = sb + s * TA_STG;
        {
            int r = tid >> 2, c4 = (tid & 3) << 2;
            cpa16(stg + TA_A_OFF + (uint32_t)((r * 20 + c4) << 2),
                  &qkv_w[(size_t)(tm + r) * C_ + k0 + c4]);
        }
        {
            int r = tid >> 4, c4 = (tid & 15) << 2;
            cpa16(stg + TA_B_OFF + (uint32_t)((r * 68 + c4) << 2),
                  &Bm[(size_t)(k0 + r) * C_ + tn + c4]);
        }
        CPA_COMMIT();
    };

    auto MMACHUNK = [&](int s) {
        const float* As = smf + (s * TA_STG + TA_A_OFF) / 4;
        const float* Bs = smf + (s * TA_STG + TA_B_OFF) / 4;
#pragma unroll
        for (int kk = 0; kk < 16; kk++) {
            u64 bv0, bv1;
            const u64* bp = reinterpret_cast<const u64*>(&Bs[kk * 68 + tx * 4]);
            bv0 = bp[0]; bv1 = bp[1];
#pragma unroll
            for (int i = 0; i < 4; i++) {
                float a = As[(ty * 4 + i) * 20 + kk];
                u64 av = pk2(a, a);
                acc[i][0] = fma2(av, bv0, acc[i][0]);
                acc[i][1] = fma2(av, bv1, acc[i][1]);
            }
        }
    };

    const int NC = C_ / 16;   // 24
    ISSUE(0, 0);
    ISSUE(1, 1);
    for (int c = 0; c < NC; c++) {
        const int s = c % 3;
        if (c == NC - 1) { CPA_WAIT0(); } else { CPA_WAIT1(); }
        __syncthreads();
        if (c + 2 < NC) ISSUE((c + 2) % 3, c + 2);
        MMACHUNK(s);
    }

    float* T = g_T + (size_t)b * 768 * C_;
#pragma unroll
    for (int i = 0; i < 4; i++) {
        int row = tm + ty * 4 + i;
        float o[4];
        upk2(acc[i][0], o[0], o[1]);
        upk2(acc[i][1], o[2], o[3]);
        *reinterpret_cast<float4*>(&T[(size_t)row * C_ + tn + tx * 4]) =
            make_float4(o[0], o[1], o[2], o[3]);
    }
}

// ============================================================================
// K4: per (b,h): Gqk + norms from T_all, softmax, fold attn into proj_w slice.
// ============================================================================
#define TB_OWK  0
#define TB_OG   18480
#define TB_OINV 20784
#define TB_OATT 20880
#define TB_OPW  23184
#define TB_SMEM ((TB_OPW + 384 * 49) * 4)

__global__ void __launch_bounds__(256)
tB_kernel(const float* __restrict__ temperature,
          const float* __restrict__ proj_w,
          const float* __restrict__ qkv_w)
{
    extern __shared__ float sm[];
    float* sWk   = sm + TB_OWK;
    float* sG    = sm + TB_OG;
    float* sInv  = sm + TB_OINV;
    float* sAttn = sm + TB_OATT;
    float* spw   = sm + TB_OPW;

    const int bh = blockIdx.x;
    const int b = bh >> 3, h = bh & 7;
    const int tid = threadIdx.x;
    const float* Tq = g_T + (size_t)b * 768 * C_ + (size_t)h * HD_ * C_;
    const float* Tk = g_T + (size_t)b * 768 * C_ + (size_t)(C_ + h * HD_) * C_;

    for (int idx = tid; idx < 48 * C_; idx += 256) {
        int e = idx / C_, k = idx % C_;
        sWk[e * 385 + k] = qkv_w[(size_t)(C_ + h * HD_ + e) * C_ + k];
    }
    for (int idx = tid; idx < 384 * 12; idx += 256) {
        int o = idx / 12, d4 = (idx % 12) * 4;
        float4 v = *reinterpret_cast<const float4*>(&proj_w[(size_t)o * C_ + h * 48 + d4]);
        float* dst = &spw[o * 49 + d4];
        dst[0] = v.x; dst[1] = v.y; dst[2] = v.z; dst[3] = v.w;
    }
    __syncthreads();

    for (int idx = tid; idx < 48 * 48; idx += 256) {
        int d = idx / 48, e = idx % 48;
        const float* tr = &Tq[(size_t)d * C_];
        const float* wr = &sWk[e * 385];
        float s = 0.0f;
#pragma unroll 8
        for (int k = 0; k < C_; k++) s += tr[k] * wr[k];
        sG[idx] = s;
    }
    if (tid < 96) {
        float s = 0.0f;
        if (tid < 48) {
            const float* tr = &Tq[(size_t)tid * C_];
            const float* wq = &qkv_w[(size_t)(h * HD_ + tid) * C_];
#pragma unroll 8
            for (int k = 0; k < C_; k++) s += tr[k] * wq[k];
        } else {
            int e = tid - 48;
            const float* tr = &Tk[(size_t)e * C_];
            const float* wr = &sWk[e * 385];
#pragma unroll 8
            for (int k = 0; k < C_; k++) s += tr[k] * wr[k];
        }
        sInv[tid] = 1.0f / fmaxf(sqrtf(s), 1e-12f);
    }
    __syncthreads();

    const float temp = temperature[h];
    if (tid < 48) {
        int d = tid;
        float l[48];
        float mx = -1e30f;
#pragma unroll
        for (int e = 0; e < 48; e++) {
            float v = sG[d * 48 + e] * sInv[d] * sInv[48 + e] * temp;
            l[e] = v;
            mx = fmaxf(mx, v);
        }
        float sum = 0.0f;
#pragma unroll
        for (int e = 0; e < 48; e++) { l[e] = expf(l[e] - mx); sum += l[e]; }
        float inv = 1.0f / sum;
#pragma unroll
        for (int e = 0; e < 48; e++) sAttn[d * 48 + e] = l[e] * inv;
    }
    __syncthreads();

    for (int o = tid; o < 384; o += 256) {
        const float* pw = &spw[o * 49];
        float* wout = &g_weff[((size_t)b * C_ + o) * C_ + h * 48];
#pragma unroll
        for (int eb = 0; eb < 6; eb++) {
            float a0 = 0, a1 = 0, a2 = 0, a3 = 0, a4 = 0, a5 = 0, a6 = 0, a7 = 0;
#pragma unroll 8
            for (int d = 0; d < 48; d++) {
                float p = pw[d];
                const float* ar = &sAttn[d * 48 + eb * 8];
                a0 += p * ar[0]; a1 += p * ar[1]; a2 += p * ar[2]; a3 += p * ar[3];
                a4 += p * ar[4]; a5 += p * ar[5]; a6 += p * ar[6]; a7 += p * ar[7];
            }
            wout[eb * 8 + 0] = a0; wout[eb * 8 + 1] = a1;
            wout[eb * 8 + 2] = a2; wout[eb * 8 + 3] = a3;
            wout[eb * 8 + 4] = a4; wout[eb * 8 + 5] = a5;
            wout[eb * 8 + 6] = a6; wout[eb * 8 + 7] = a7;
        }
    }
}

// ============================================================================
// K5: W_final[b] = W_eff[b] @ W_v -> bf16 planes. f32x2 GEMM 128x128.
// ============================================================================
__global__ void __launch_bounds__(256)
wfinal_kernel(const float* __restrict__ qkv_w)
{
    const int BM = 128, BN = 128, BK = 16;
    __shared__ __align__(16) float As[BK][BM];
    __shared__ __align__(16) float Bs[BK][BN];

    const int b = blockIdx.z;
    const float* A = g_weff + (size_t)b * C_ * C_;
    const float* Bm = qkv_w + (size_t)2 * C_ * C_;
    const int tm = blockIdx.y * BM, tn = blockIdx.x * BN;
    const int tid = threadIdx.x;
    const int tx = tid & 15, ty = tid >> 4;

    u64 acc[8][4];
#pragma unroll
    for (int i = 0; i < 8; i++)
#pragma unroll
        for (int p = 0; p < 4; p++) acc[i][p] = 0ull;

    for (int k0 = 0; k0 < C_; k0 += BK) {
#pragma unroll
        for (int i = 0; i < 2; i++) {
            int f4 = tid + 256 * i;
            int r = f4 >> 2, c4 = (f4 & 3) << 2;
            float4 v = *reinterpret_cast<const float4*>(&A[(size_t)(tm + r) * C_ + k0 + c4]);
            As[c4 + 0][r] = v.x; As[c4 + 1][r] = v.y;
            As[c4 + 2][r] = v.z; As[c4 + 3][r] = v.w;
        }
#pragma unroll
        for (int i = 0; i < 2; i++) {
            int f4 = tid + 256 * i;
            int r = f4 >> 5, c4 = (f4 & 31) << 2;
            *reinterpret_cast<float4*>(&Bs[r][c4]) =
                *reinterpret_cast<const float4*>(&Bm[(size_t)(k0 + r) * C_ + tn + c4]);
        }
        __syncthreads();
#pragma unroll
        for (int kk = 0; kk < BK; kk++) {
            u64 av[8];
#pragma unroll
            for (int i = 0; i < 8; i++) { float a = As[kk][ty * 8 + i]; av[i] = pk2(a, a); }
            u64 bv[4];
            const u64* bp = reinterpret_cast<const u64*>(&Bs[kk][tx * 8]);
#pragma unroll
            for (int p = 0; p < 4; p++) bv[p] = bp[p];
#pragma unroll
            for (int i = 0; i < 8; i++)
#pragma unroll
                for (int p = 0; p < 4; p++)
                    acc[i][p] = fma2(av[i], bv[p], acc[i][p]);
        }
        __syncthreads();
    }

#pragma unroll
    for (int i = 0; i < 8; i++) {
        int row = tm + ty * 8 + i;
        float o[8];
#pragma unroll
        for (int p = 0; p < 4; p++) upk2(acc[i][p], o[2 * p], o[2 * p + 1]);
        uint32_t h0, l0, h1, l1, h2, l2, h3, l3;
        split2(h0, l0, o[0], o[1]);
        split2(h1, l1, o[2], o[3]);
        split2(h2, l2, o[4], o[5]);
        split2(h3, l3, o[6], o[7]);
        size_t ro = ((size_t)b * C_ + row) * (C_ / 2) + ((tn + tx * 8) >> 1);
        *reinterpret_cast<uint4*>(g_wf_hi + ro) = make_uint4(h0, h1, h2, h3);
        *reinterpret_cast<uint4*>(g_wf_lo + ro) = make_uint4(l0, l1, l2, l3);
    }
}

// ===========================================================================
// K6: out[b] = W_final[b] @ x[b] + proj_b.  128x128 tile, BK=32, 3-stage
// cp.async, 2 CTAs/SM. Stage: A hi/lo [128][40]h + B hi/lo [32][136]h.
// ===========================================================================
#define OA_HI 0
#define OA_LO 10240
#define OB_HI 20480
#define OB_LO 29184
#define OSTG  37888
#define GEMM_SMEM (3 * OSTG)   // 113664 -> 2 CTAs/SM

__global__ void __launch_bounds__(256, 2)
gemm_out(const __nv_bfloat16* __restrict__ Ah, const __nv_bfloat16* __restrict__ Al,
         const __nv_bfloat16* __restrict__ Bh, const __nv_bfloat16* __restrict__ Bl,
         int M, int N, int K, long long sA, long long sB,
         float* __restrict__ Of, long long sC, const float* __restrict__ bias)
{
    extern __shared__ char smem[];
    const uint32_t sb = smem_u32(smem);
    const int tid = threadIdx.x;
    const int wid = tid >> 5, lane = tid & 31;

    const int z = blockIdx.z;
    Ah += (size_t)z * sA;  Al += (size_t)z * sA;
    Bh += (size_t)z * sB;  Bl += (size_t)z * sB;
    const int tm = blockIdx.x * 128, tn = blockIdx.y * 128;
    const int warp_m = (wid >> 2) * 64, warp_n = (wid & 3) * 32;

    float acc[4][4][4];
#pragma unroll
    for (int i = 0; i < 4; i++)
#pragma unroll
        for (int j = 0; j < 4; j++)
#pragma unroll
            for (int p = 0; p < 4; p++) acc[i][j][p] = 0.0f;

    auto ISSUE = [&](int s, int c) {
        const int k0 = c * 32;
        const uint32_t stg = sb + s * OSTG;
#pragma unroll
        for (int i = 0; i < 4; i++) {
            int id = tid + 256 * i;
            int pl = id >> 9, rem = id & 511, row = rem >> 2, ch = rem & 3;
            const __nv_bfloat16* src = (pl ? Al : Ah) + (size_t)(tm + row) * K + k0 + ch * 8;
            cpa16(stg + OA_HI + pl * (OA_LO - OA_HI) + (uint32_t)((row * 40 + ch * 8) << 1), src);
        }
#pragma unroll
        for (int i = 0; i < 4; i++) {
            int id = tid + 256 * i;
            int pl = id >> 9, rem = id & 511, row = rem >> 4, ch = rem & 15;
            const __nv_bfloat16* src = (pl ? Bl : Bh) + (size_t)(k0 + row) * N + tn + ch * 8;
            cpa16(stg + OB_HI + pl * (OB_LO - OB_HI) + (uint32_t)((row * 136 + ch * 8) << 1), src);
        }
        CPA_COMMIT();
    };

    auto MMASTEP = [&](int s, int ks) {
        const uint32_t stg = sb + s * OSTG;
        uint32_t bh[4][2], bl[4][2];
        {
            uint32_t krow = (uint32_t)(ks * 16 + (lane & 7) + (((lane >> 3) & 1) << 3));
            uint32_t ncol = (uint32_t)(warp_n + ((lane >> 4) << 3));
            uint32_t bd  = stg + OB_HI + ((krow * 136 + ncol) << 1);
            uint32_t bdl = bd + (OB_LO - OB_HI);
            uint32_t r4[4];
            ldsm4t(r4, bd);
            bh[0][0] = r4[0]; bh[0][1] = r4[1]; bh[1][0] = r4[2]; bh[1][1] = r4[3];
            ldsm4t(r4, bd + 32);
            bh[2][0] = r4[0]; bh[2][1] = r4[1]; bh[3][0] = r4[2]; bh[3][1] = r4[3];
            ldsm4t(r4, bdl);
            bl[0][0] = r4[0]; bl[0][1] = r4[1]; bl[1][0] = r4[2]; bl[1][1] = r4[3];
            ldsm4t(r4, bdl + 32);
            bl[2][0] = r4[0]; bl[2][1] = r4[1]; bl[3][0] = r4[2]; bl[3][1] = r4[3];
        }
        const uint32_t arow = (uint32_t)(warp_m + (lane & 15));
        const uint32_t akoff = (uint32_t)(ks * 16 + ((lane >> 4) << 3));
#pragma unroll
        for (int mf = 0; mf < 4; mf++) {
            uint32_t ah[4], al[4];
            uint32_t ad = stg + OA_HI + (((arow + mf * 16) * 40 + akoff) << 1);
            ldsm4(ah, ad);
            ldsm4(al, ad + (OA_LO - OA_HI));
#pragma unroll
            for (int nf = 0; nf < 4; nf++) {
                mma16816(acc[mf][nf], ah, bh[nf]);
                mma16816(acc[mf][nf], ah, bl[nf]);
                mma16816(acc[mf][nf], al, bh[nf]);
            }
        }
    };

    const int NC = K >> 5;   // 12
    ISSUE(0, 0);
    ISSUE(1, 1);
    for (int c = 0; c < NC; c++) {
        const int s = c % 3;
        if (c == NC - 1) { CPA_WAIT0(); } else { CPA_WAIT1(); }
        __syncthreads();
        if (c + 2 < NC) ISSUE((c + 2) % 3, c + 2);
        MMASTEP(s, 0);
        MMASTEP(s, 1);
        __syncthreads();
    }

    // Epilogue staged via smem fp32 [128][132]
    float* cs = reinterpret_cast<float*>(smem);
    const int g = lane >> 2, t2 = (lane & 3) * 2;
#pragma unroll
    for (int mf = 0; mf < 4; mf++)
#pragma unroll
        for (int nf = 0; nf < 4; nf++) {
            int r0 = warp_m + mf * 16 + g;
            int c0 = warp_n + nf * 8 + t2;
            cs[r0 * 132 + c0]           = acc[mf][nf][0];
            cs[r0 * 132 + c0 + 1]       = acc[mf][nf][1];
            cs[(r0 + 8) * 132 + c0]     = acc[mf][nf][2];
            cs[(r0 + 8) * 132 + c0 + 1] = acc[mf][nf][3];
        }
    __syncthreads();
    {
        const int r = tid >> 1, cb = (tid & 1) * 64;
        const float bval = bias[tm + r];
        float* op = Of + (size_t)z * sC + (size_t)(tm + r) * N + tn + cb;
        const float* ip = &cs[r * 132 + cb];
#pragma unroll
        for (int j = 0; j < 16; j++) {
            float4 v = make_float4(ip[4 * j] + bval, ip[4 * j + 1] + bval,
                                   ip[4 * j + 2] + bval, ip[4 * j + 3] + bval);
            reinterpret_cast<float4*>(op)[j] = v;
        }
    }
}

// ============================================================================
extern "C" void kernel_launch(void* const* d_in, const int* in_sizes, int n_in,
                              void* d_out, int out_size)
{
    const float* x           = (const float*)d_in[0];
    const float* qkv_w       = (const float*)d_in[1];
    const float* proj_w      = (const float*)d_in[2];
    const float* proj_b      = (const float*)d_in[3];
    const float* temperature = (const float*)d_in[4];
    float* out = (float*)d_out;

    void* p;
    cudaGetSymbolAddress(&p, g_x_hi);  uint32_t* x_hi = (uint32_t*)p;
    cudaGetSymbolAddress(&p, g_x_lo);  uint32_t* x_lo = (uint32_t*)p;
    cudaGetSymbolAddress(&p, g_wf_hi); uint32_t* wf_hi = (uint32_t*)p;
    cudaGetSymbolAddress(&p, g_wf_lo); uint32_t* wf_lo = (uint32_t*)p;

    cudaFuncSetAttribute((const void*)x2_cp,
                         cudaFuncAttributeMaxDynamicSharedMemorySize, X2_SMEM);
    cudaFuncSetAttribute((const void*)tA_gemm,
                         cudaFuncAttributeMaxDynamicSharedMemorySize, TA_SMEM);
    cudaFuncSetAttribute((const void*)tB_kernel,
                         cudaFuncAttributeMaxDynamicSharedMemorySize, TB_SMEM);
    cudaFuncSetAttribute((const void*)gemm_out,
                         cudaFuncAttributeMaxDynamicSharedMemorySize, GEMM_SMEM);

    // K0: x -> bf16 hi/lo planes
    split_planes<<<2048, 256>>>((const float2*)x, x_hi, x_lo, B_ * C_ * HW_ / 2);

    // K1: X2 upper-block partials (Gram of x)
    x2_cp<<<dim3(6 * NS2, B_), 256, X2_SMEM>>>(
        (const __nv_bfloat16*)x_hi, (const __nv_bfloat16*)x_lo);

    // K2: reduce + mirror
    x2_reduce<<<B_ * C_ * C_ / 256, 256>>>();

    // K3: T_all = qkv_w[0:768] @ X2
    tA_gemm<<<dim3(6, 12, B_), 256, TA_SMEM>>>(qkv_w);

    // K4: Gram->softmax->W_eff fold
    tB_kernel<<<B_ * NH_, 256, TB_SMEM>>>(temperature, proj_w, qkv_w);

    // K5: W_final = W_eff @ W_v  -> bf16 planes
    wfinal_kernel<<<dim3(3, 3, B_), 256>>>(qkv_w);

    // K6: out = W_final @ x + proj_b
    gemm_out<<<dim3(C_ / 128, HW_ / 128, B_), 256, GEMM_SMEM>>>(
        (const __nv_bfloat16*)wf_hi, (const __nv_bfloat16*)wf_lo,
        (const __nv_bfloat16*)x_hi, (const __nv_bfloat16*)x_lo,
        C_, HW_, C_, (long long)C_ * C_, (long long)C_ * HW_,
        out, (long long)C_ * HW_, proj_b);
}